// round 16
// baseline (speedup 1.0000x reference)
#include <cuda_runtime.h>
#include <cuda_fp16.h>
#include <cuda_bf16.h>
#include <cstdint>

#define BB 4
#define DIM 256
#define NN 2048
#define HEADS 8
#define DH 64
#define HID 512
#define O3 1536
#define SCALE 0.125f
#define LOG2E 1.4426950408889634f
#define BH (BB * HEADS)

typedef unsigned long long ull;

// Scratch (__device__ globals; allocation-free rule)
__device__ __half g_wq16[O3 * DIM];
__device__ __half g_wo16[DIM * HID];
__device__ __half g_x16[(size_t)BB * DIM * NN];        // x f16 [b][c][n]
__device__ __half g_qT[(size_t)BB * HEADS * DH * NN];  // [bh][c][n]
__device__ __half g_kT[(size_t)BB * HEADS * DH * NN];
__device__ __half g_vT[(size_t)BB * HEADS * DH * NN];
__device__ __half g_opart[(size_t)2 * BB * NN * HID];  // unnormalized O partials f16 [z][b][n][512]
__device__ float  g_lpart[(size_t)2 * BH * NN];        // denominator partials [z][bh][n]
__device__ __half g_a16[(size_t)BB * NN * HID];        // attn out f16 [b][n][512]

// ---------------- helpers ----------------
__device__ __forceinline__ uint32_t pkh2(float lo, float hi) {
    uint32_t r; asm("cvt.rn.f16x2.f32 %0, %1, %2;" : "=r"(r) : "f"(hi), "f"(lo)); return r;
}
__device__ __forceinline__ uint32_t ex2h2(uint32_t x) {
    uint32_t y; asm("ex2.approx.f16x2 %0, %1;" : "=r"(y) : "r"(x)); return y;
}
__device__ __forceinline__ uint32_t smem_u32(const void* p) {
    uint32_t a; asm("{ .reg .u64 t; cvta.to.shared.u64 t, %1; cvt.u32.u64 %0, t; }" : "=r"(a) : "l"(p));
    return a;
}
__device__ __forceinline__ uint32_t sw128(uint32_t b) { return b ^ ((b >> 3) & 0x70); }

__device__ __forceinline__ void cpa16(uint32_t dst, const void* src) {
    asm volatile("cp.async.cg.shared.global [%0], [%1], 16;" :: "r"(dst), "l"(src));
}
#define CP_COMMIT() asm volatile("cp.async.commit_group;" ::: "memory")
#define CP_WAIT0()  asm volatile("cp.async.wait_group 0;" ::: "memory")

__device__ __forceinline__ void ldsm4(uint32_t* r, uint32_t a) {
    asm volatile("ldmatrix.sync.aligned.m8n8.x4.shared.b16 {%0,%1,%2,%3}, [%4];"
                 : "=r"(r[0]), "=r"(r[1]), "=r"(r[2]), "=r"(r[3]) : "r"(a));
}
__device__ __forceinline__ void ldsm4t(uint32_t* r, uint32_t a) {
    asm volatile("ldmatrix.sync.aligned.m8n8.x4.trans.shared.b16 {%0,%1,%2,%3}, [%4];"
                 : "=r"(r[0]), "=r"(r[1]), "=r"(r[2]), "=r"(r[3]) : "r"(a));
}
__device__ __forceinline__ void mma16816(float* d, const uint32_t* a, uint32_t b0, uint32_t b1) {
    asm volatile("mma.sync.aligned.m16n8k16.row.col.f32.f16.f16.f32 "
                 "{%0,%1,%2,%3},{%4,%5,%6,%7},{%8,%9},{%0,%1,%2,%3};"
                 : "+f"(d[0]), "+f"(d[1]), "+f"(d[2]), "+f"(d[3])
                 : "r"(a[0]), "r"(a[1]), "r"(a[2]), "r"(a[3]), "r"(b0), "r"(b1));
}
__device__ __forceinline__ void mma16816h(uint32_t* d, const uint32_t* a, uint32_t b0, uint32_t b1) {
    asm volatile("mma.sync.aligned.m16n8k16.row.col.f16.f16.f16.f16 "
                 "{%0,%1},{%2,%3,%4,%5},{%6,%7},{%0,%1};"
                 : "+r"(d[0]), "+r"(d[1])
                 : "r"(a[0]), "r"(a[1]), "r"(a[2]), "r"(a[3]), "r"(b0), "r"(b1));
}

// ---------------------------------------------------------------------------
// Merged prep: x f16 convert + weight f16 convert (one launch)
// ---------------------------------------------------------------------------
#define XWORK ((size_t)BB * DIM * NN / 4)        // 1,048,576
#define WWORK (O3 * DIM + DIM * HID)             // 524,288

__global__ void prep_kernel(const float* __restrict__ x, __half* __restrict__ x16,
                            const float* __restrict__ wq, const float* __restrict__ wo,
                            __half* __restrict__ wq16, __half* __restrict__ wo16)
{
    size_t gid = (size_t)blockIdx.x * blockDim.x + threadIdx.x;
    if (gid < XWORK) {
        size_t i = gid * 4;
        float4 v = *(const float4*)(x + i);
        *(uint2*)(x16 + i) = make_uint2(pkh2(v.x, v.y), pkh2(v.z, v.w));
    } else {
        int i = (int)(gid - XWORK);
        if (i < O3 * DIM) {
            float v = wq[i];
            if (i < HID * DIM) v *= (SCALE * LOG2E);
            wq16[i] = __float2half_rn(v);
        } else {
            int j = i - O3 * DIM;
            wo16[j] = __float2half_rn(wo[j]);
        }
    }
}

// ---------------------------------------------------------------------------
// QKV GEMM (unchanged from round 15): warp shape M=32 x N=64.
// ---------------------------------------------------------------------------
__global__ void __launch_bounds__(256, 2) qkv_gemm_kernel(
    const __half* __restrict__ A, const __half* __restrict__ Bx,
    __half* __restrict__ qT, __half* __restrict__ kT, __half* __restrict__ vT)
{
    __shared__ __align__(1024) __half Ws[2][8192];  // [128 o][64 k]
    __shared__ __align__(1024) __half Xh[2][8192];  // [64 k][128 n], two 8KB n-half pages

    const int t    = threadIdx.x;
    const int w    = t >> 5;
    const int lane = t & 31;
    const int wo   = w >> 1;
    const int wn   = w & 1;
    const int n0   = blockIdx.x * 128;
    const int o0   = blockIdx.y * 128;
    const int b    = blockIdx.z;

    const uint32_t wsb = smem_u32(Ws);
    const uint32_t xhb = smem_u32(Xh);

    float oc[2][8][4];
#pragma unroll
    for (int mf = 0; mf < 2; mf++)
#pragma unroll
        for (int i = 0; i < 8; i++)
#pragma unroll
            for (int j = 0; j < 4; j++) oc[mf][i][j] = 0.f;

    const int rr = t >> 1, kh = t & 1;
    const __half* Abase = A + (size_t)(o0 + rr) * DIM + kh * 32;
    const int arow0 = wo * 32 + (lane & 15);
    const int ach   = (lane >> 4) & 1;
    const int kcrow = lane & 15;
    const int kmo   = ((lane >> 4) & 1) * 16;

    const int nsteps = DIM / 64;

    {
#pragma unroll
        for (int i = 0; i < 4; i++) {
            uint32_t so = sw128(rr * 128 + kh * 64 + i * 16);
            cpa16(wsb + so, Abase + i * 8);
        }
#pragma unroll
        for (int i = 0; i < 4; i++) {
            int idx = t + i * 256;
            int c = idx >> 4, ch = idx & 15;
            uint32_t so = (uint32_t)((ch >> 3) * 8192) + sw128(c * 128 + (ch & 7) * 16);
            cpa16(xhb + so, Bx + ((size_t)b * DIM + c) * NN + n0 + ch * 8);
        }
        CP_COMMIT();
    }

    for (int s = 0; s < nsteps; s++) {
        const int cur = s & 1;
        CP_WAIT0();
        __syncthreads();
        if (s + 1 < nsteps) {
            const int kt = (s + 1) * 64;
            const uint32_t bufo = (uint32_t)((cur ^ 1) * 16384);
#pragma unroll
            for (int i = 0; i < 4; i++) {
                uint32_t so = bufo + sw128(rr * 128 + kh * 64 + i * 16);
                cpa16(wsb + so, Abase + kt + i * 8);
            }
#pragma unroll
            for (int i = 0; i < 4; i++) {
                int idx = t + i * 256;
                int c = idx >> 4, ch = idx & 15;
                uint32_t so = bufo + (uint32_t)((ch >> 3) * 8192) + sw128(c * 128 + (ch & 7) * 16);
                cpa16(xhb + so, Bx + ((size_t)b * DIM + kt + c) * NN + n0 + ch * 8);
            }
            CP_COMMIT();
        }
        const uint32_t wcb = wsb + (uint32_t)(cur * 16384);
        const uint32_t hcb = xhb + (uint32_t)(cur * 16384) + (uint32_t)(wn * 8192);
#pragma unroll
        for (int kc = 0; kc < 4; kc++) {
            uint32_t a0[4], a1[4];
            ldsm4(a0, wcb + sw128((arow0)      * 128 + kc * 32 + ach * 16));
            ldsm4(a1, wcb + sw128((arow0 + 16) * 128 + kc * 32 + ach * 16));
#pragma unroll
            for (int nb = 0; nb < 4; nb++) {
                uint32_t bf[4];
                ldsm4t(bf, hcb + sw128((kc * 16 + kcrow) * 128 + nb * 32 + kmo));
                mma16816(oc[0][2 * nb],     a0, bf[0], bf[1]);
                mma16816(oc[0][2 * nb + 1], a0, bf[2], bf[3]);
                mma16816(oc[1][2 * nb],     a1, bf[0], bf[1]);
                mma16816(oc[1][2 * nb + 1], a1, bf[2], bf[3]);
            }
        }
    }

    const int sec = o0 >> 9;
    __half* base = (sec == 0 ? qT : (sec == 1 ? kT : vT));
#pragma unroll
    for (int mf = 0; mf < 2; mf++) {
        const int local = (o0 & 511) + wo * 32 + mf * 16;
        const int h     = local >> 6;
        const int bh    = b * HEADS + h;
        const int c     = (local & 63) + (lane >> 2);
        __half* d0 = base + ((size_t)bh * DH + c) * NN + n0 + wn * 64 + 2 * (lane & 3);
        __half* d8 = d0 + (size_t)8 * NN;
#pragma unroll
        for (int nb = 0; nb < 8; nb++) {
            *(uint32_t*)(d0 + nb * 8) = pkh2(oc[mf][nb][0], oc[mf][nb][1]);
            *(uint32_t*)(d8 + nb * 8) = pkh2(oc[mf][nb][2], oc[mf][nb][3]);
        }
    }
}

// ---------------------------------------------------------------------------
// Out projection: tile 128(o) x 64(n), 128 threads, 4 warps, M=32 x N=64.
// Grid 256 CTAs -> fills the chip.
// ---------------------------------------------------------------------------
__global__ void __launch_bounds__(128, 3) out_gemm_kernel(
    const __half* __restrict__ A, const __half* __restrict__ Bh,
    float* __restrict__ outF, const float* __restrict__ bias)
{
    __shared__ __align__(1024) __half Ws[2][8192];  // [128 o][64 k]
    __shared__ __align__(1024) __half Xh[2][4096];  // [64 n][64 k]

    const int t    = threadIdx.x;
    const int w    = t >> 5;       // o-group 0..3
    const int lane = t & 31;
    const int n0   = blockIdx.x * 64;
    const int o0   = blockIdx.y * 128;
    const int b    = blockIdx.z;
    const int K    = HID;

    const uint32_t wsb = smem_u32(Ws);
    const uint32_t xhb = smem_u32(Xh);

    float oc[2][8][4];
#pragma unroll
    for (int mf = 0; mf < 2; mf++)
#pragma unroll
        for (int i = 0; i < 8; i++)
#pragma unroll
            for (int j = 0; j < 4; j++) oc[mf][i][j] = 0.f;

    const int arow0 = w * 32 + (lane & 15);
    const int ach   = (lane >> 4) & 1;
    const int brow0 = (lane & 7) + ((lane >> 4) & 1) * 8;
    const int bko   = ((lane >> 3) & 1) * 16;

    // W load: 128 rows x 8 chunks = 1024 chunks, 8/thread (1 row per thread)
    // X load: 64 rows x 8 chunks = 512 chunks, 4/thread
    const __half* Abase  = A  + (size_t)(o0 + t) * K;                 // row t
    const int xr = t >> 1, xh = t & 1;
    const __half* Bhbase = Bh + ((size_t)b * NN + n0 + xr) * K + xh * 32;

    const int nsteps = K >> 6;

#pragma unroll
    for (int i = 0; i < 8; i++)
        cpa16(wsb + sw128(t * 128 + i * 16), Abase + i * 8);
#pragma unroll
    for (int i = 0; i < 4; i++)
        cpa16(xhb + sw128(xr * 128 + xh * 64 + i * 16), Bhbase + i * 8);
    CP_COMMIT();

    for (int s = 0; s < nsteps; s++) {
        const int cur = s & 1;
        CP_WAIT0();
        __syncthreads();
        if (s + 1 < nsteps) {
            const int kt = (s + 1) * 64;
#pragma unroll
            for (int i = 0; i < 8; i++)
                cpa16(wsb + (uint32_t)((cur ^ 1) * 16384) + sw128(t * 128 + i * 16),
                      Abase + kt + i * 8);
#pragma unroll
            for (int i = 0; i < 4; i++)
                cpa16(xhb + (uint32_t)((cur ^ 1) * 8192) + sw128(xr * 128 + xh * 64 + i * 16),
                      Bhbase + kt + i * 8);
            CP_COMMIT();
        }
        const uint32_t wcb = wsb + (uint32_t)(cur * 16384);
        const uint32_t hcb = xhb + (uint32_t)(cur * 8192);
#pragma unroll
        for (int kc = 0; kc < 4; kc++) {
            uint32_t a0[4], a1[4];
            ldsm4(a0, wcb + sw128((arow0)      * 128 + kc * 32 + ach * 16));
            ldsm4(a1, wcb + sw128((arow0 + 16) * 128 + kc * 32 + ach * 16));
#pragma unroll
            for (int nb = 0; nb < 4; nb++) {
                uint32_t bf[4];
                ldsm4(bf, hcb + sw128((nb * 16 + brow0) * 128 + kc * 32 + bko));
                mma16816(oc[0][2 * nb],     a0, bf[0], bf[1]);
                mma16816(oc[0][2 * nb + 1], a0, bf[2], bf[3]);
                mma16816(oc[1][2 * nb],     a1, bf[0], bf[1]);
                mma16816(oc[1][2 * nb + 1], a1, bf[2], bf[3]);
            }
        }
    }

#pragma unroll
    for (int mf = 0; mf < 2; mf++) {
        const int o  = o0 + w * 32 + mf * 16 + (lane >> 2);
        const float b0 = bias[o], b8 = bias[o + 8];
        float* r0 = outF + ((size_t)b * DIM + o) * NN + n0 + 2 * (lane & 3);
        float* r8 = r0 + (size_t)8 * NN;
#pragma unroll
        for (int nb = 0; nb < 8; nb++) {
            *(float2*)(r0 + nb * 8) = make_float2(oc[mf][nb][0] + b0, oc[mf][nb][1] + b0);
            *(float2*)(r8 + nb * 8) = make_float2(oc[mf][nb][2] + b8, oc[mf][nb][3] + b8);
        }
    }
}

// ---------------------------------------------------------------------------
// FA2 flash attention (unchanged from round 15): split-K z=2, f16 O partials.
// ---------------------------------------------------------------------------
#define QT 128
#define KT 64
#define NKT (NN / KT / 2)   // 16 tiles per key-half

__global__ void __launch_bounds__(128, 3) attn_kernel(
    const __half* __restrict__ qT, const __half* __restrict__ kT,
    const __half* __restrict__ vT, __half* __restrict__ opart,
    float* __restrict__ lpart)
{
    __shared__ __align__(1024) __half Qs[8192];      // [64 c][128 q], 2 pages by q-half
    __shared__ __align__(1024) __half Ks[2][4096];   // [64 c][64 m]
    __shared__ __align__(1024) __half Vs[2][4096];

    const int t    = threadIdx.x;
    const int w    = t >> 5;
    const int lane = t & 31;
    const int bh   = blockIdx.y;
    const int b    = bh >> 3;
    const int h    = bh & 7;
    const int q0   = blockIdx.x * QT;
    const int z    = blockIdx.z;
    const int zoff = z * (NN / 2);

    const __half* Qg = qT + (size_t)bh * DH * NN;
    const __half* Kg = kT + (size_t)bh * DH * NN;
    const __half* Vg = vT + (size_t)bh * DH * NN;

    const uint32_t qb = smem_u32(Qs);
    const uint32_t kb = smem_u32(Ks);
    const uint32_t vb = smem_u32(Vs);

#define LOADKV(bufo, kt0) do {                                         \
        _Pragma("unroll")                                              \
        for (int i = 0; i < 4; i++) {                                  \
            int idx = t + i * 128;                                     \
            int c = idx >> 3, ch = idx & 7;                            \
            uint32_t so = (bufo) + sw128(c * 128 + ch * 16);           \
            const size_t gs = (size_t)c * NN + zoff + (kt0) + ch * 8;  \
            cpa16(kb + so, Kg + gs);                                   \
            cpa16(vb + so, Vg + gs);                                   \
        }                                                              \
    } while (0)

#pragma unroll
    for (int i = 0; i < 8; i++) {
        int idx = t + i * 128;
        int c = idx >> 4, ch = idx & 15;
        uint32_t so = (uint32_t)((ch >> 3) * 8192) + sw128(c * 128 + (ch & 7) * 16);
        *(uint4*)((char*)Qs + so) = *(const uint4*)(Qg + (size_t)c * NN + q0 + ch * 8);
    }
    LOADKV(0u, 0);
    CP_COMMIT();
    __syncthreads();

    uint32_t qa[4][2][4];
    {
        const int crow = (lane & 7) + ((lane >> 4) & 1) * 8;
        const uint32_t qpage = qb + (uint32_t)((w >> 1) * 8192);
#pragma unroll
        for (int kc = 0; kc < 4; kc++)
#pragma unroll
            for (int mf = 0; mf < 2; mf++) {
                int colb = ((w & 1) * 32 + mf * 16 + ((lane >> 3) & 1) * 8) * 2;
                ldsm4t(qa[kc][mf], qpage + sw128((kc * 16 + crow) * 128 + colb));
            }
    }

    float oc[2][8][4];
#pragma unroll
    for (int mf = 0; mf < 2; mf++)
#pragma unroll
        for (int i = 0; i < 8; i++)
#pragma unroll
            for (int j = 0; j < 4; j++) oc[mf][i][j] = 0.f;
    float lrA[2] = {0.f, 0.f}, lrB[2] = {0.f, 0.f};

    const int kc_row = lane & 15;
    const int km_off = ((lane >> 4) & 1) * 16;
    const int vc_row = (lane & 7) + ((lane >> 4) & 1) * 8;
    const int vm_off = ((lane >> 3) & 1) * 16;

    for (int s = 0; s < NKT; s++) {
        const int cur = s & 1;
        CP_WAIT0();
        __syncthreads();
        if (s + 1 < NKT) {
            LOADKV((uint32_t)((cur ^ 1) * 8192), (s + 1) * KT);
            CP_COMMIT();
        }
        const uint32_t kcb = kb + (uint32_t)(cur * 8192);
        const uint32_t vcb = vb + (uint32_t)(cur * 8192);

        uint32_t ps[2][4][4];
#pragma unroll
        for (int mf = 0; mf < 2; mf++)
#pragma unroll
            for (int kn = 0; kn < 4; kn++)
#pragma unroll
                for (int i = 0; i < 4; i++) ps[mf][kn][i] = 0u;
#pragma unroll
        for (int kc = 0; kc < 4; kc++)
#pragma unroll
            for (int kn = 0; kn < 4; kn++) {
                uint32_t bf[4];
                ldsm4t(bf, kcb + sw128((kc * 16 + kc_row) * 128 + kn * 32 + km_off));
#pragma unroll
                for (int mf = 0; mf < 2; mf++) {
                    mma16816h(&ps[mf][kn][0], qa[kc][mf], bf[0], bf[1]);
                    mma16816h(&ps[mf][kn][2], qa[kc][mf], bf[2], bf[3]);
                }
            }

#pragma unroll
        for (int mf = 0; mf < 2; mf++) {
            __half2 aA = __float2half2_rn(0.f), aB = __float2half2_rn(0.f);
#pragma unroll
            for (int kn = 0; kn < 4; kn++) {
                ps[mf][kn][0] = ex2h2(ps[mf][kn][0]);
                ps[mf][kn][1] = ex2h2(ps[mf][kn][1]);
                ps[mf][kn][2] = ex2h2(ps[mf][kn][2]);
                ps[mf][kn][3] = ex2h2(ps[mf][kn][3]);
                aA = __hadd2(aA, __hadd2(*(__half2*)&ps[mf][kn][0], *(__half2*)&ps[mf][kn][2]));
                aB = __hadd2(aB, __hadd2(*(__half2*)&ps[mf][kn][1], *(__half2*)&ps[mf][kn][3]));
            }
            float2 fA = __half22float2(aA); lrA[mf] += fA.x + fA.y;
            float2 fB = __half22float2(aB); lrB[mf] += fB.x + fB.y;
        }

#pragma unroll
        for (int j = 0; j < 4; j++)
#pragma unroll
            for (int ncv = 0; ncv < 4; ncv++) {
                uint32_t bf[4];
                ldsm4(bf, vcb + sw128((ncv * 16 + vc_row) * 128 + j * 32 + vm_off));
#pragma unroll
                for (int mf = 0; mf < 2; mf++) {
                    mma16816(oc[mf][2 * ncv],     ps[mf][j], bf[0], bf[1]);
                    mma16816(oc[mf][2 * ncv + 1], ps[mf][j], bf[2], bf[3]);
                }
            }
    }

#pragma unroll
    for (int mf = 0; mf < 2; mf++) {
        float la = lrA[mf], lb = lrB[mf];
        la += __shfl_xor_sync(0xFFFFFFFF, la, 1);
        la += __shfl_xor_sync(0xFFFFFFFF, la, 2);
        lb += __shfl_xor_sync(0xFFFFFFFF, lb, 1);
        lb += __shfl_xor_sync(0xFFFFFFFF, lb, 2);

        const int q = q0 + w * 32 + mf * 16 + (lane >> 2);
        if ((lane & 3) == 0) {
            float* lp = lpart + ((size_t)z * BH + bh) * NN;
            lp[q]     = la;
            lp[q + 8] = lb;
        }
        __half* op0 = opart + (((size_t)z * BB + b) * NN + q) * HID + h * DH + 2 * (lane & 3);
        __half* op8 = op0 + (size_t)8 * HID;
#pragma unroll
        for (int nb = 0; nb < 8; nb++) {
            *(uint32_t*)(op0 + nb * 8) = pkh2(oc[mf][nb][0], oc[mf][nb][1]);
            *(uint32_t*)(op8 + nb * 8) = pkh2(oc[mf][nb][2], oc[mf][nb][3]);
        }
    }
#undef LOADKV
}

// ---------------------------------------------------------------------------
// Split-K reduction: a16 = (O0 + O1) / (l0 + l1). 1 thread = 16 channels.
// ---------------------------------------------------------------------------
__global__ void reduce_attn_kernel(const __half* __restrict__ opart,
                                   const float* __restrict__ lpart,
                                   __half* __restrict__ a16)
{
    const size_t gid = (size_t)blockIdx.x * blockDim.x + threadIdx.x;
    const int   c    = (int)(gid & 31) * 16;     // 32 threads per row of 512 ch
    const size_t qn  = gid >> 5;                 // b*NN + q
    const int   q    = (int)(qn & (NN - 1));
    const int   b    = (int)(qn >> 11);
    const int   bh   = b * HEADS + (c >> 6);     // 16 channels stay within one head

    const size_t oi = qn * HID + c;
    const uint4 h0a = *(const uint4*)(opart + oi);
    const uint4 h0b = *(const uint4*)(opart + oi + 8);
    const uint4 h1a = *(const uint4*)(opart + (size_t)BB * NN * HID + oi);
    const uint4 h1b = *(const uint4*)(opart + (size_t)BB * NN * HID + oi + 8);
    const float l0 = lpart[(size_t)bh * NN + q];
    const float l1 = lpart[(size_t)(BH + bh) * NN + q];
    const float inv = 1.f / (l0 + l1);

#define RED4(dst, ha, hb) do {                                                        \
        float2 a0 = __half22float2(*(__half2*)&(ha).x), b0 = __half22float2(*(__half2*)&(hb).x); \
        float2 a1 = __half22float2(*(__half2*)&(ha).y), b1 = __half22float2(*(__half2*)&(hb).y); \
        float2 a2 = __half22float2(*(__half2*)&(ha).z), b2 = __half22float2(*(__half2*)&(hb).z); \
        float2 a3 = __half22float2(*(__half2*)&(ha).w), b3 = __half22float2(*(__half2*)&(hb).w); \
        (dst).x = pkh2((a0.x + b0.x) * inv, (a0.y + b0.y) * inv);                     \
        (dst).y = pkh2((a1.x + b1.x) * inv, (a1.y + b1.y) * inv);                     \
        (dst).z = pkh2((a2.x + b2.x) * inv, (a2.y + b2.y) * inv);                     \
        (dst).w = pkh2((a3.x + b3.x) * inv, (a3.y + b3.y) * inv);                     \
    } while (0)

    uint4 r0, r1;
    RED4(r0, h0a, h1a);
    RED4(r1, h0b, h1b);
    *(uint4*)(a16 + oi)     = r0;
    *(uint4*)(a16 + oi + 8) = r1;
#undef RED4
}

// ---------------------------------------------------------------------------
extern "C" void kernel_launch(void* const* d_in, const int* in_sizes, int n_in,
                              void* d_out, int out_size)
{
    const float* x     = (const float*)d_in[0];
    const float* w_qkv = (const float*)d_in[1];
    const float* w_out = (const float*)d_in[2];
    const float* b_out = (const float*)d_in[3];
    float* out = (float*)d_out;

    __half *wq16, *wo16, *x16, *qT, *kT, *vT, *a16, *opart;
    float *lpart;
    cudaGetSymbolAddress((void**)&wq16,  g_wq16);
    cudaGetSymbolAddress((void**)&wo16,  g_wo16);
    cudaGetSymbolAddress((void**)&x16,   g_x16);
    cudaGetSymbolAddress((void**)&qT,    g_qT);
    cudaGetSymbolAddress((void**)&kT,    g_kT);
    cudaGetSymbolAddress((void**)&vT,    g_vT);
    cudaGetSymbolAddress((void**)&a16,   g_a16);
    cudaGetSymbolAddress((void**)&opart, g_opart);
    cudaGetSymbolAddress((void**)&lpart, g_lpart);

    {
        const size_t total = XWORK + WWORK;
        prep_kernel<<<(unsigned)(total / 256), 256>>>(x, x16, w_qkv, w_out, wq16, wo16);
    }
    {
        dim3 grid(NN / 128, O3 / 128, BB);
        qkv_gemm_kernel<<<grid, 256>>>(wq16, x16, qT, kT, vT);
    }
    {
        dim3 grid(NN / QT, BH, 2);
        attn_kernel<<<grid, 128>>>(qT, kT, vT, opart, lpart);
    }
    {
        const size_t threads = (size_t)BB * NN * HID / 16;   // 262,144
        reduce_attn_kernel<<<(unsigned)(threads / 256), 256>>>(opart, lpart, a16);
    }
    {
        dim3 grid(NN / 64, DIM / 128, BB);
        out_gemm_kernel<<<grid, 128>>>(wo16, a16, out, b_out);
    }
}

// round 17
// speedup vs baseline: 1.0491x; 1.0491x over previous
#include <cuda_runtime.h>
#include <cuda_fp16.h>
#include <cuda_bf16.h>
#include <cstdint>

#define BB 4
#define DIM 256
#define NN 2048
#define HEADS 8
#define DH 64
#define HID 512
#define O3 1536
#define SCALE 0.125f
#define LOG2E 1.4426950408889634f
#define BH (BB * HEADS)

typedef unsigned long long ull;

// Scratch (__device__ globals; allocation-free rule)
__device__ __half g_wq16[O3 * DIM];
__device__ __half g_wo16[DIM * HID];
__device__ __half g_x16[(size_t)BB * DIM * NN];        // x f16 [b][c][n]
__device__ __half g_qT[(size_t)BB * HEADS * DH * NN];  // [bh][c][n]
__device__ __half g_kT[(size_t)BB * HEADS * DH * NN];
__device__ __half g_vT[(size_t)BB * HEADS * DH * NN];
__device__ __half g_opart[(size_t)2 * BB * NN * HID];  // unnormalized O partials f16 [z][b][n][512]
__device__ float  g_lpart[(size_t)2 * BH * NN];        // denominator partials [z][bh][n]

// ---------------- helpers ----------------
__device__ __forceinline__ uint32_t pkh2(float lo, float hi) {
    uint32_t r; asm("cvt.rn.f16x2.f32 %0, %1, %2;" : "=r"(r) : "f"(hi), "f"(lo)); return r;
}
__device__ __forceinline__ uint32_t ex2h2(uint32_t x) {
    uint32_t y; asm("ex2.approx.f16x2 %0, %1;" : "=r"(y) : "r"(x)); return y;
}
__device__ __forceinline__ uint32_t smem_u32(const void* p) {
    uint32_t a; asm("{ .reg .u64 t; cvta.to.shared.u64 t, %1; cvt.u32.u64 %0, t; }" : "=r"(a) : "l"(p));
    return a;
}
__device__ __forceinline__ uint32_t sw128(uint32_t b) { return b ^ ((b >> 3) & 0x70); }

__device__ __forceinline__ void cpa16(uint32_t dst, const void* src) {
    asm volatile("cp.async.cg.shared.global [%0], [%1], 16;" :: "r"(dst), "l"(src));
}
#define CP_COMMIT() asm volatile("cp.async.commit_group;" ::: "memory")
#define CP_WAIT0()  asm volatile("cp.async.wait_group 0;" ::: "memory")

__device__ __forceinline__ void ldsm4(uint32_t* r, uint32_t a) {
    asm volatile("ldmatrix.sync.aligned.m8n8.x4.shared.b16 {%0,%1,%2,%3}, [%4];"
                 : "=r"(r[0]), "=r"(r[1]), "=r"(r[2]), "=r"(r[3]) : "r"(a));
}
__device__ __forceinline__ void ldsm4t(uint32_t* r, uint32_t a) {
    asm volatile("ldmatrix.sync.aligned.m8n8.x4.trans.shared.b16 {%0,%1,%2,%3}, [%4];"
                 : "=r"(r[0]), "=r"(r[1]), "=r"(r[2]), "=r"(r[3]) : "r"(a));
}
__device__ __forceinline__ void mma16816(float* d, const uint32_t* a, uint32_t b0, uint32_t b1) {
    asm volatile("mma.sync.aligned.m16n8k16.row.col.f32.f16.f16.f32 "
                 "{%0,%1,%2,%3},{%4,%5,%6,%7},{%8,%9},{%0,%1,%2,%3};"
                 : "+f"(d[0]), "+f"(d[1]), "+f"(d[2]), "+f"(d[3])
                 : "r"(a[0]), "r"(a[1]), "r"(a[2]), "r"(a[3]), "r"(b0), "r"(b1));
}
__device__ __forceinline__ void mma16816h(uint32_t* d, const uint32_t* a, uint32_t b0, uint32_t b1) {
    asm volatile("mma.sync.aligned.m16n8k16.row.col.f16.f16.f16.f16 "
                 "{%0,%1},{%2,%3,%4,%5},{%6,%7},{%0,%1};"
                 : "+r"(d[0]), "+r"(d[1])
                 : "r"(a[0]), "r"(a[1]), "r"(a[2]), "r"(a[3]), "r"(b0), "r"(b1));
}

// ---------------------------------------------------------------------------
// Merged prep: x f16 convert + weight f16 convert (one launch)
// ---------------------------------------------------------------------------
#define XWORK ((size_t)BB * DIM * NN / 4)        // 1,048,576
#define WWORK (O3 * DIM + DIM * HID)             // 524,288

__global__ void prep_kernel(const float* __restrict__ x, __half* __restrict__ x16,
                            const float* __restrict__ wq, const float* __restrict__ wo,
                            __half* __restrict__ wq16, __half* __restrict__ wo16)
{
    size_t gid = (size_t)blockIdx.x * blockDim.x + threadIdx.x;
    if (gid < XWORK) {
        size_t i = gid * 4;
        float4 v = *(const float4*)(x + i);
        *(uint2*)(x16 + i) = make_uint2(pkh2(v.x, v.y), pkh2(v.z, v.w));
    } else {
        int i = (int)(gid - XWORK);
        if (i < O3 * DIM) {
            float v = wq[i];
            if (i < HID * DIM) v *= (SCALE * LOG2E);
            wq16[i] = __float2half_rn(v);
        } else {
            int j = i - O3 * DIM;
            wo16[j] = __float2half_rn(wo[j]);
        }
    }
}

// ---------------------------------------------------------------------------
// QKV GEMM (round-15 exact): warp shape M=32 x N=64.
// ---------------------------------------------------------------------------
__global__ void __launch_bounds__(256, 2) qkv_gemm_kernel(
    const __half* __restrict__ A, const __half* __restrict__ Bx,
    __half* __restrict__ qT, __half* __restrict__ kT, __half* __restrict__ vT)
{
    __shared__ __align__(1024) __half Ws[2][8192];  // [128 o][64 k]
    __shared__ __align__(1024) __half Xh[2][8192];  // [64 k][128 n], two 8KB n-half pages

    const int t    = threadIdx.x;
    const int w    = t >> 5;
    const int lane = t & 31;
    const int wo   = w >> 1;
    const int wn   = w & 1;
    const int n0   = blockIdx.x * 128;
    const int o0   = blockIdx.y * 128;
    const int b    = blockIdx.z;

    const uint32_t wsb = smem_u32(Ws);
    const uint32_t xhb = smem_u32(Xh);

    float oc[2][8][4];
#pragma unroll
    for (int mf = 0; mf < 2; mf++)
#pragma unroll
        for (int i = 0; i < 8; i++)
#pragma unroll
            for (int j = 0; j < 4; j++) oc[mf][i][j] = 0.f;

    const int rr = t >> 1, kh = t & 1;
    const __half* Abase = A + (size_t)(o0 + rr) * DIM + kh * 32;
    const int arow0 = wo * 32 + (lane & 15);
    const int ach   = (lane >> 4) & 1;
    const int kcrow = lane & 15;
    const int kmo   = ((lane >> 4) & 1) * 16;

    const int nsteps = DIM / 64;

    {
#pragma unroll
        for (int i = 0; i < 4; i++) {
            uint32_t so = sw128(rr * 128 + kh * 64 + i * 16);
            cpa16(wsb + so, Abase + i * 8);
        }
#pragma unroll
        for (int i = 0; i < 4; i++) {
            int idx = t + i * 256;
            int c = idx >> 4, ch = idx & 15;
            uint32_t so = (uint32_t)((ch >> 3) * 8192) + sw128(c * 128 + (ch & 7) * 16);
            cpa16(xhb + so, Bx + ((size_t)b * DIM + c) * NN + n0 + ch * 8);
        }
        CP_COMMIT();
    }

    for (int s = 0; s < nsteps; s++) {
        const int cur = s & 1;
        CP_WAIT0();
        __syncthreads();
        if (s + 1 < nsteps) {
            const int kt = (s + 1) * 64;
            const uint32_t bufo = (uint32_t)((cur ^ 1) * 16384);
#pragma unroll
            for (int i = 0; i < 4; i++) {
                uint32_t so = bufo + sw128(rr * 128 + kh * 64 + i * 16);
                cpa16(wsb + so, Abase + kt + i * 8);
            }
#pragma unroll
            for (int i = 0; i < 4; i++) {
                int idx = t + i * 256;
                int c = idx >> 4, ch = idx & 15;
                uint32_t so = bufo + (uint32_t)((ch >> 3) * 8192) + sw128(c * 128 + (ch & 7) * 16);
                cpa16(xhb + so, Bx + ((size_t)b * DIM + kt + c) * NN + n0 + ch * 8);
            }
            CP_COMMIT();
        }
        const uint32_t wcb = wsb + (uint32_t)(cur * 16384);
        const uint32_t hcb = xhb + (uint32_t)(cur * 16384) + (uint32_t)(wn * 8192);
#pragma unroll
        for (int kc = 0; kc < 4; kc++) {
            uint32_t a0[4], a1[4];
            ldsm4(a0, wcb + sw128((arow0)      * 128 + kc * 32 + ach * 16));
            ldsm4(a1, wcb + sw128((arow0 + 16) * 128 + kc * 32 + ach * 16));
#pragma unroll
            for (int nb = 0; nb < 4; nb++) {
                uint32_t bf[4];
                ldsm4t(bf, hcb + sw128((kc * 16 + kcrow) * 128 + nb * 32 + kmo));
                mma16816(oc[0][2 * nb],     a0, bf[0], bf[1]);
                mma16816(oc[0][2 * nb + 1], a0, bf[2], bf[3]);
                mma16816(oc[1][2 * nb],     a1, bf[0], bf[1]);
                mma16816(oc[1][2 * nb + 1], a1, bf[2], bf[3]);
            }
        }
    }

    const int sec = o0 >> 9;
    __half* base = (sec == 0 ? qT : (sec == 1 ? kT : vT));
#pragma unroll
    for (int mf = 0; mf < 2; mf++) {
        const int local = (o0 & 511) + wo * 32 + mf * 16;
        const int h     = local >> 6;
        const int bh    = b * HEADS + h;
        const int c     = (local & 63) + (lane >> 2);
        __half* d0 = base + ((size_t)bh * DH + c) * NN + n0 + wn * 64 + 2 * (lane & 3);
        __half* d8 = d0 + (size_t)8 * NN;
#pragma unroll
        for (int nb = 0; nb < 8; nb++) {
            *(uint32_t*)(d0 + nb * 8) = pkh2(oc[mf][nb][0], oc[mf][nb][1]);
            *(uint32_t*)(d8 + nb * 8) = pkh2(oc[mf][nb][2], oc[mf][nb][3]);
        }
    }
}

// ---------------------------------------------------------------------------
// Fused out projection: B tiles built inline from opart z0/z1 + lpart.
// Each K-step (64 ch) = exactly one head -> per-row scalar inv per step.
// Tile 128(o) x 128(n), warp shape M=32 x N=64 (round-15 proven).
// ---------------------------------------------------------------------------
__global__ void __launch_bounds__(256, 2) out_gemm_kernel(
    const __half* __restrict__ A, const __half* __restrict__ opart,
    const float* __restrict__ lpart, float* __restrict__ outF,
    const float* __restrict__ bias)
{
    __shared__ __align__(1024) __half Ws[2][8192];   // [128 o][64 k]
    __shared__ __align__(1024) __half Xh[2][8192];   // [128 n][64 k]

    const int t    = threadIdx.x;
    const int w    = t >> 5;
    const int lane = t & 31;
    const int wo   = w >> 1;
    const int wn   = w & 1;
    const int n0   = blockIdx.x * 128;
    const int o0   = blockIdx.y * 128;
    const int b    = blockIdx.z;
    const int K    = HID;

    const uint32_t wsb = smem_u32(Ws);
    const uint32_t xhb = smem_u32(Xh);

    float oc[2][8][4];
#pragma unroll
    for (int mf = 0; mf < 2; mf++)
#pragma unroll
        for (int i = 0; i < 8; i++)
#pragma unroll
            for (int j = 0; j < 4; j++) oc[mf][i][j] = 0.f;

    const int arow0 = wo * 32 + (lane & 15);
    const int ach   = (lane >> 4) & 1;
    const int brow0 = (lane & 7) + ((lane >> 4) & 1) * 8;
    const int bko   = ((lane >> 3) & 1) * 16;

    const int rr = t >> 1, kh = t & 1;
    const __half* Abase = A + (size_t)(o0 + rr) * K + kh * 32;
    const __half* B0 = opart + ((size_t)b * NN + n0 + rr) * HID + kh * 32;
    const __half* B1 = B0 + (size_t)BB * NN * HID;
    const float* lp0 = lpart + (size_t)(b * HEADS) * NN + n0 + rr;   // + s*NN per head
    const float* lp1 = lp0 + (size_t)BH * NN;

    const int nsteps = K >> 6;   // 8, head s per step

    // prologue: W stage 0 via cp.async; B(0) + l(0) staged in registers
    uint4 rB0[4], rB1[4];
#pragma unroll
    for (int i = 0; i < 4; i++) {
        rB0[i] = *(const uint4*)(B0 + i * 8);
        rB1[i] = *(const uint4*)(B1 + i * 8);
    }
    float l0 = lp0[0], l1 = lp1[0];
#pragma unroll
    for (int i = 0; i < 4; i++)
        cpa16(wsb + sw128(rr * 128 + kh * 64 + i * 16), Abase + i * 8);
    CP_COMMIT();

    for (int s = 0; s < nsteps; s++) {
        const int cur = s & 1;

        // normalize staged B: (o0+o1) * 1/(l0+l1) -> f16
        const float inv = 1.f / (l0 + l1);
        uint4 nB[4];
#pragma unroll
        for (int i = 0; i < 4; i++) {
            float2 a0 = __half22float2(*(__half2*)&rB0[i].x), c0 = __half22float2(*(__half2*)&rB1[i].x);
            float2 a1 = __half22float2(*(__half2*)&rB0[i].y), c1 = __half22float2(*(__half2*)&rB1[i].y);
            float2 a2 = __half22float2(*(__half2*)&rB0[i].z), c2 = __half22float2(*(__half2*)&rB1[i].z);
            float2 a3 = __half22float2(*(__half2*)&rB0[i].w), c3 = __half22float2(*(__half2*)&rB1[i].w);
            nB[i].x = pkh2((a0.x + c0.x) * inv, (a0.y + c0.y) * inv);
            nB[i].y = pkh2((a1.x + c1.x) * inv, (a1.y + c1.y) * inv);
            nB[i].z = pkh2((a2.x + c2.x) * inv, (a2.y + c2.y) * inv);
            nB[i].w = pkh2((a3.x + c3.x) * inv, (a3.y + c3.y) * inv);
        }

        CP_WAIT0();              // W(s) landed
        __syncthreads();         // all warps done with buffers of step s-1

        // store normalized B tile
#pragma unroll
        for (int i = 0; i < 4; i++)
            *(uint4*)((char*)Xh + (uint32_t)(cur * 16384) + sw128(rr * 128 + kh * 64 + i * 16)) = nB[i];

        // prefetch step s+1: B+l into regs, W via cp.async into other buffer
        if (s + 1 < nsteps) {
            const int kt = (s + 1) * 64;
#pragma unroll
            for (int i = 0; i < 4; i++) {
                rB0[i] = *(const uint4*)(B0 + kt + i * 8);
                rB1[i] = *(const uint4*)(B1 + kt + i * 8);
            }
            l0 = lp0[(size_t)(s + 1) * NN];
            l1 = lp1[(size_t)(s + 1) * NN];
#pragma unroll
            for (int i = 0; i < 4; i++)
                cpa16(wsb + (uint32_t)((cur ^ 1) * 16384) + sw128(rr * 128 + kh * 64 + i * 16),
                      Abase + kt + i * 8);
            CP_COMMIT();
        }
        __syncthreads();         // B tile visible

        const uint32_t wcb = wsb + (uint32_t)(cur * 16384);
        const uint32_t hcb = xhb + (uint32_t)(cur * 16384);
#pragma unroll
        for (int kc = 0; kc < 4; kc++) {
            uint32_t a0[4], a1[4];
            ldsm4(a0, wcb + sw128((arow0)      * 128 + kc * 32 + ach * 16));
            ldsm4(a1, wcb + sw128((arow0 + 16) * 128 + kc * 32 + ach * 16));
#pragma unroll
            for (int nb = 0; nb < 4; nb++) {
                uint32_t bf[4];
                ldsm4(bf, hcb + sw128((wn * 64 + nb * 16 + brow0) * 128 + kc * 32 + bko));
                mma16816(oc[0][2 * nb],     a0, bf[0], bf[1]);
                mma16816(oc[0][2 * nb + 1], a0, bf[2], bf[3]);
                mma16816(oc[1][2 * nb],     a1, bf[0], bf[1]);
                mma16816(oc[1][2 * nb + 1], a1, bf[2], bf[3]);
            }
        }
    }

#pragma unroll
    for (int mf = 0; mf < 2; mf++) {
        const int o  = o0 + wo * 32 + mf * 16 + (lane >> 2);
        const float b0 = bias[o], b8 = bias[o + 8];
        float* r0 = outF + ((size_t)b * DIM + o) * NN + n0 + wn * 64 + 2 * (lane & 3);
        float* r8 = r0 + (size_t)8 * NN;
#pragma unroll
        for (int nb = 0; nb < 8; nb++) {
            *(float2*)(r0 + nb * 8) = make_float2(oc[mf][nb][0] + b0, oc[mf][nb][1] + b0);
            *(float2*)(r8 + nb * 8) = make_float2(oc[mf][nb][2] + b8, oc[mf][nb][3] + b8);
        }
    }
}

// ---------------------------------------------------------------------------
// FA2 flash attention (round-15 exact): split-K z=2, f16 O partials.
// ---------------------------------------------------------------------------
#define QT 128
#define KT 64
#define NKT (NN / KT / 2)   // 16 tiles per key-half

__global__ void __launch_bounds__(128, 3) attn_kernel(
    const __half* __restrict__ qT, const __half* __restrict__ kT,
    const __half* __restrict__ vT, __half* __restrict__ opart,
    float* __restrict__ lpart)
{
    __shared__ __align__(1024) __half Qs[8192];      // [64 c][128 q], 2 pages by q-half
    __shared__ __align__(1024) __half Ks[2][4096];   // [64 c][64 m]
    __shared__ __align__(1024) __half Vs[2][4096];

    const int t    = threadIdx.x;
    const int w    = t >> 5;
    const int lane = t & 31;
    const int bh   = blockIdx.y;
    const int b    = bh >> 3;
    const int h    = bh & 7;
    const int q0   = blockIdx.x * QT;
    const int z    = blockIdx.z;
    const int zoff = z * (NN / 2);

    const __half* Qg = qT + (size_t)bh * DH * NN;
    const __half* Kg = kT + (size_t)bh * DH * NN;
    const __half* Vg = vT + (size_t)bh * DH * NN;

    const uint32_t qb = smem_u32(Qs);
    const uint32_t kb = smem_u32(Ks);
    const uint32_t vb = smem_u32(Vs);

#define LOADKV(bufo, kt0) do {                                         \
        _Pragma("unroll")                                              \
        for (int i = 0; i < 4; i++) {                                  \
            int idx = t + i * 128;                                     \
            int c = idx >> 3, ch = idx & 7;                            \
            uint32_t so = (bufo) + sw128(c * 128 + ch * 16);           \
            const size_t gs = (size_t)c * NN + zoff + (kt0) + ch * 8;  \
            cpa16(kb + so, Kg + gs);                                   \
            cpa16(vb + so, Vg + gs);                                   \
        }                                                              \
    } while (0)

#pragma unroll
    for (int i = 0; i < 8; i++) {
        int idx = t + i * 128;
        int c = idx >> 4, ch = idx & 15;
        uint32_t so = (uint32_t)((ch >> 3) * 8192) + sw128(c * 128 + (ch & 7) * 16);
        *(uint4*)((char*)Qs + so) = *(const uint4*)(Qg + (size_t)c * NN + q0 + ch * 8);
    }
    LOADKV(0u, 0);
    CP_COMMIT();
    __syncthreads();

    uint32_t qa[4][2][4];
    {
        const int crow = (lane & 7) + ((lane >> 4) & 1) * 8;
        const uint32_t qpage = qb + (uint32_t)((w >> 1) * 8192);
#pragma unroll
        for (int kc = 0; kc < 4; kc++)
#pragma unroll
            for (int mf = 0; mf < 2; mf++) {
                int colb = ((w & 1) * 32 + mf * 16 + ((lane >> 3) & 1) * 8) * 2;
                ldsm4t(qa[kc][mf], qpage + sw128((kc * 16 + crow) * 128 + colb));
            }
    }

    float oc[2][8][4];
#pragma unroll
    for (int mf = 0; mf < 2; mf++)
#pragma unroll
        for (int i = 0; i < 8; i++)
#pragma unroll
            for (int j = 0; j < 4; j++) oc[mf][i][j] = 0.f;
    float lrA[2] = {0.f, 0.f}, lrB[2] = {0.f, 0.f};

    const int kc_row = lane & 15;
    const int km_off = ((lane >> 4) & 1) * 16;
    const int vc_row = (lane & 7) + ((lane >> 4) & 1) * 8;
    const int vm_off = ((lane >> 3) & 1) * 16;

    for (int s = 0; s < NKT; s++) {
        const int cur = s & 1;
        CP_WAIT0();
        __syncthreads();
        if (s + 1 < NKT) {
            LOADKV((uint32_t)((cur ^ 1) * 8192), (s + 1) * KT);
            CP_COMMIT();
        }
        const uint32_t kcb = kb + (uint32_t)(cur * 8192);
        const uint32_t vcb = vb + (uint32_t)(cur * 8192);

        uint32_t ps[2][4][4];
#pragma unroll
        for (int mf = 0; mf < 2; mf++)
#pragma unroll
            for (int kn = 0; kn < 4; kn++)
#pragma unroll
                for (int i = 0; i < 4; i++) ps[mf][kn][i] = 0u;
#pragma unroll
        for (int kc = 0; kc < 4; kc++)
#pragma unroll
            for (int kn = 0; kn < 4; kn++) {
                uint32_t bf[4];
                ldsm4t(bf, kcb + sw128((kc * 16 + kc_row) * 128 + kn * 32 + km_off));
#pragma unroll
                for (int mf = 0; mf < 2; mf++) {
                    mma16816h(&ps[mf][kn][0], qa[kc][mf], bf[0], bf[1]);
                    mma16816h(&ps[mf][kn][2], qa[kc][mf], bf[2], bf[3]);
                }
            }

#pragma unroll
        for (int mf = 0; mf < 2; mf++) {
            __half2 aA = __float2half2_rn(0.f), aB = __float2half2_rn(0.f);
#pragma unroll
            for (int kn = 0; kn < 4; kn++) {
                ps[mf][kn][0] = ex2h2(ps[mf][kn][0]);
                ps[mf][kn][1] = ex2h2(ps[mf][kn][1]);
                ps[mf][kn][2] = ex2h2(ps[mf][kn][2]);
                ps[mf][kn][3] = ex2h2(ps[mf][kn][3]);
                aA = __hadd2(aA, __hadd2(*(__half2*)&ps[mf][kn][0], *(__half2*)&ps[mf][kn][2]));
                aB = __hadd2(aB, __hadd2(*(__half2*)&ps[mf][kn][1], *(__half2*)&ps[mf][kn][3]));
            }
            float2 fA = __half22float2(aA); lrA[mf] += fA.x + fA.y;
            float2 fB = __half22float2(aB); lrB[mf] += fB.x + fB.y;
        }

#pragma unroll
        for (int j = 0; j < 4; j++)
#pragma unroll
            for (int ncv = 0; ncv < 4; ncv++) {
                uint32_t bf[4];
                ldsm4(bf, vcb + sw128((ncv * 16 + vc_row) * 128 + j * 32 + vm_off));
#pragma unroll
                for (int mf = 0; mf < 2; mf++) {
                    mma16816(oc[mf][2 * ncv],     ps[mf][j], bf[0], bf[1]);
                    mma16816(oc[mf][2 * ncv + 1], ps[mf][j], bf[2], bf[3]);
                }
            }
    }

#pragma unroll
    for (int mf = 0; mf < 2; mf++) {
        float la = lrA[mf], lb = lrB[mf];
        la += __shfl_xor_sync(0xFFFFFFFF, la, 1);
        la += __shfl_xor_sync(0xFFFFFFFF, la, 2);
        lb += __shfl_xor_sync(0xFFFFFFFF, lb, 1);
        lb += __shfl_xor_sync(0xFFFFFFFF, lb, 2);

        const int q = q0 + w * 32 + mf * 16 + (lane >> 2);
        if ((lane & 3) == 0) {
            float* lp = lpart + ((size_t)z * BH + bh) * NN;
            lp[q]     = la;
            lp[q + 8] = lb;
        }
        __half* op0 = opart + (((size_t)z * BB + b) * NN + q) * HID + h * DH + 2 * (lane & 3);
        __half* op8 = op0 + (size_t)8 * HID;
#pragma unroll
        for (int nb = 0; nb < 8; nb++) {
            *(uint32_t*)(op0 + nb * 8) = pkh2(oc[mf][nb][0], oc[mf][nb][1]);
            *(uint32_t*)(op8 + nb * 8) = pkh2(oc[mf][nb][2], oc[mf][nb][3]);
        }
    }
#undef LOADKV
}

// ---------------------------------------------------------------------------
extern "C" void kernel_launch(void* const* d_in, const int* in_sizes, int n_in,
                              void* d_out, int out_size)
{
    const float* x     = (const float*)d_in[0];
    const float* w_qkv = (const float*)d_in[1];
    const float* w_out = (const float*)d_in[2];
    const float* b_out = (const float*)d_in[3];
    float* out = (float*)d_out;

    __half *wq16, *wo16, *x16, *qT, *kT, *vT, *opart;
    float *lpart;
    cudaGetSymbolAddress((void**)&wq16,  g_wq16);
    cudaGetSymbolAddress((void**)&wo16,  g_wo16);
    cudaGetSymbolAddress((void**)&x16,   g_x16);
    cudaGetSymbolAddress((void**)&qT,    g_qT);
    cudaGetSymbolAddress((void**)&kT,    g_kT);
    cudaGetSymbolAddress((void**)&vT,    g_vT);
    cudaGetSymbolAddress((void**)&opart, g_opart);
    cudaGetSymbolAddress((void**)&lpart, g_lpart);

    {
        const size_t total = XWORK + WWORK;
        prep_kernel<<<(unsigned)(total / 256), 256>>>(x, x16, w_qkv, w_out, wq16, wo16);
    }
    {
        dim3 grid(NN / 128, O3 / 128, BB);
        qkv_gemm_kernel<<<grid, 256>>>(wq16, x16, qT, kT, vT);
    }
    {
        dim3 grid(NN / QT, BH, 2);
        attn_kernel<<<grid, 128>>>(qT, kT, vT, opart, lpart);
    }
    {
        dim3 grid(NN / 128, DIM / 128, BB);
        out_gemm_kernel<<<grid, 256>>>(wo16, opart, lpart, out, b_out);
    }
}